// round 5
// baseline (speedup 1.0000x reference)
#include <cuda_runtime.h>
#include <math.h>

// Problem constants
#define NB   2
#define NS   128
#define NROW (NB*NS)        // 256 rows (b*s)
#define NN   512            // feature dim
#define NM   1024           // 2*N output cols of GEMM
#define NK   512            // contraction dim

#define SAMPLE_ELEMS (NROW*NN)               // 131072
#define STD_ELEMS    ((long long)NROW*NN*NN) // 67108864

#define GBM 32
#define GBN 64
#define GBK 32
#define KS  4
#define KPER (NK/KS)        // 128
#define KITERS (KPER/GBK)   // 4

#define GEMM_CTAS 512       // 16 x 8 x 4
#define FILL_CTAS 1536
#define TOTAL_CTAS (GEMM_CTAS + FILL_CTAS)

// Scratch (no allocations allowed)
__device__ float g_part[KS * NROW * NM];   // 4 MB split-K partials
__device__ float g_var[NROW * NN];         // 0.5 MB (kept for debug; diag now fused)

// ---------------- Fused kernel: GEMM roles + zero-fill roles ----------------
__global__ __launch_bounds__(256)
void fused_kernel(const float* __restrict__ A, const float* __restrict__ W,
                  float* __restrict__ P, float4* __restrict__ out4) {
    const int bid = blockIdx.x;
    const int tid = threadIdx.x;

    if (bid >= GEMM_CTAS) {
        // -------- Zero-fill role: stream zeros over std_mat (256 MB) --------
        const long long total4 = STD_ELEMS >> 2;            // 16777216
        const long long stride = (long long)FILL_CTAS * 256;
        const float4 z = make_float4(0.f, 0.f, 0.f, 0.f);
        for (long long idx = (long long)(bid - GEMM_CTAS) * 256 + tid;
             idx < total4; idx += stride) {
            __stcs(&out4[idx], z);
        }
        return;
    }

    // -------- GEMM role: split-K partial tile --------
    __shared__ __align__(16) float As[2][GBK][GBM + 2];
    __shared__ __align__(16) float Bs[2][GBK][GBN + 4];

    const int bx = bid & 15;          // N tile (0..15)
    const int by = (bid >> 4) & 7;    // M tile (0..7)
    const int bz = bid >> 7;          // K split (0..3)

    const int ty = tid >> 4;          // 0..15 -> rows ty*2, ty*2+1
    const int tx = tid & 15;          // cols tx*4 .. tx*4+3

    const int lr = tid >> 3;          // 0..31
    const int lk = (tid & 7) << 2;    // 0,4,...,28

    const float* Ag  = A + (size_t)(by * GBM + lr) * NK + bz * KPER;
    const float* Wg0 = W + (size_t)(bx * GBN + lr) * NK + bz * KPER;
    const float* Wg1 = Wg0 + (size_t)32 * NK;

    float acc[2][4] = {};

    // Prologue: tile 0 -> buffer 0
    float4 a4 = *(const float4*)(Ag  + lk);
    float4 b0 = *(const float4*)(Wg0 + lk);
    float4 b1 = *(const float4*)(Wg1 + lk);
    #pragma unroll
    for (int q = 0; q < 4; q++) {
        As[0][lk + q][lr]      = ((const float*)&a4)[q];
        Bs[0][lk + q][lr]      = ((const float*)&b0)[q];
        Bs[0][lk + q][lr + 32] = ((const float*)&b1)[q];
    }
    __syncthreads();

    int buf = 0;
    for (int it = 0; it < KITERS; it++) {
        float4 na, nb0, nb1;
        const bool more = (it + 1 < KITERS);
        if (more) {
            na  = *(const float4*)(Ag  + (it + 1) * GBK + lk);
            nb0 = *(const float4*)(Wg0 + (it + 1) * GBK + lk);
            nb1 = *(const float4*)(Wg1 + (it + 1) * GBK + lk);
        }

        #pragma unroll
        for (int kk = 0; kk < GBK; kk++) {
            float2 a2 = *(const float2*)&As[buf][kk][ty * 2];
            float4 w4 = *(const float4*)&Bs[buf][kk][tx * 4];
            acc[0][0] = fmaf(a2.x, w4.x, acc[0][0]);
            acc[0][1] = fmaf(a2.x, w4.y, acc[0][1]);
            acc[0][2] = fmaf(a2.x, w4.z, acc[0][2]);
            acc[0][3] = fmaf(a2.x, w4.w, acc[0][3]);
            acc[1][0] = fmaf(a2.y, w4.x, acc[1][0]);
            acc[1][1] = fmaf(a2.y, w4.y, acc[1][1]);
            acc[1][2] = fmaf(a2.y, w4.z, acc[1][2]);
            acc[1][3] = fmaf(a2.y, w4.w, acc[1][3]);
        }

        if (more) {
            const int nb = buf ^ 1;
            #pragma unroll
            for (int q = 0; q < 4; q++) {
                As[nb][lk + q][lr]      = ((const float*)&na)[q];
                Bs[nb][lk + q][lr]      = ((const float*)&nb0)[q];
                Bs[nb][lk + q][lr + 32] = ((const float*)&nb1)[q];
            }
            __syncthreads();
            buf = nb;
        }
    }

    float* Pp = P + (size_t)bz * (NROW * NM);
    #pragma unroll
    for (int i = 0; i < 2; i++) {
        const int row = by * GBM + ty * 2 + i;
        float4 v = make_float4(acc[i][0], acc[i][1], acc[i][2], acc[i][3]);
        *(float4*)(Pp + (size_t)row * NM + bx * GBN + tx * 4) = v;
    }
}

// ---------------- Pointwise: reduce split-K + var/mu/sample + diagonal ------
__device__ __forceinline__ float softplus_f(float x) {
    return fmaxf(x, 0.0f) + log1pf(expf(-fabsf(x)));
}

__global__ __launch_bounds__(256)
void pointwise_kernel(const float* __restrict__ P,
                      const float* __restrict__ bias,
                      const float* __restrict__ eps,
                      float* __restrict__ out_sample,
                      float* __restrict__ out_mu,
                      float* __restrict__ out_std) {
    int idx = blockIdx.x * blockDim.x + threadIdx.x;
    if (idx >= SAMPLE_ELEMS) return;
    int row = idx >> 9;          // global row /512
    int i   = idx & (NN - 1);

    float s_var = bias[i];
    float s_mu  = bias[NN + i];
    #pragma unroll
    for (int z = 0; z < KS; z++) {
        const float* Pz = P + (size_t)z * (NROW * NM) + (size_t)row * NM;
        s_var += Pz[i];
        s_mu  += Pz[NN + i];
    }
    float var = softplus_f(s_var);
    out_mu[idx]     = s_mu;
    out_sample[idx] = fmaf(sqrtf(var), eps[idx], s_mu);
    // Diagonal injection into std_mat (overwrites the zero written by fill role)
    out_std[(size_t)idx * NN + i] = var;
}

extern "C" void kernel_launch(void* const* d_in, const int* in_sizes, int n_in,
                              void* d_out, int out_size) {
    const float* x   = (const float*)d_in[0];
    const float* W   = (const float*)d_in[1];
    const float* b   = (const float*)d_in[2];
    const float* eps = (const float*)d_in[3];

    float* out        = (float*)d_out;
    float* out_sample = out;
    float* out_mu     = out + SAMPLE_ELEMS;
    float* out_std    = out + 2 * SAMPLE_ELEMS;

    float* part;  cudaGetSymbolAddress((void**)&part, g_part);

    // 1) Fused: GEMM (512 CTAs) co-resident with std_mat zero-fill (1536 CTAs)
    fused_kernel<<<TOTAL_CTAS, 256>>>(x, W, part, (float4*)out_std);

    // 2) pointwise: split-K reduce + sample/mu + diagonal scatter
    pointwise_kernel<<<SAMPLE_ELEMS / 256, 256>>>(part, b, eps,
                                                  out_sample, out_mu, out_std);
}